// round 1
// baseline (speedup 1.0000x reference)
#include <cuda_runtime.h>

// Problem constants (fixed shapes from reference)
#define ROWS    4096
#define COLS    16384
#define MCOL    100
#define THREADS 256
#define NWARP   (THREADS / 32)
#define WSTRIDE 104            // floats per per-warp histogram (bins 0..100, padded)

// Output layout: [roc (ROWS*100) | deriv (ROWS*100) | trapz_roc (ROWS) | trapz_deriv (ROWS)]
#define OUT_DER (ROWS * MCOL)
#define OUT_T1  (2 * ROWS * MCOL)
#define OUT_T2  (2 * ROWS * MCOL + ROWS)

// Binning trick:
//   w = fma(v, 99/256, 3 - 2^-10)  lies in [2.999, 3.386) c [2,4)  (single binade)
//   mantissa(w) = 2^22 + (99v - 0.25)*2^14 (+-rounding)
//   (bits(w) >> 14) & 0x3FF = 256 + k0 with k0 = floor(99v - 0.25 + eps_tiny)
//   true bin = count(t[j] < v) is guaranteed in {k0+1, k0+2}, resolved by ONE
//   compare against t[k0+1]  =>  exact searchsorted(t, v, 'left') semantics.
// idx4 = ((bits>>14)&0x3FF)<<2 = (bits>>12)&0xFFC = 4*(k0+256); byte offsets are
// pre-biased by -1020 so that idx4 indexes t[k0+1] / hist[k0+1] directly.

__global__ void __launch_bounds__(THREADS, 1)
roc_hist_kernel(const float* __restrict__ x,
                const float* __restrict__ y,
                float* __restrict__ out)
{
    __shared__ float tS[104];              // thresholds t[0..99], padded
    __shared__ float wh[NWARP * WSTRIDE];  // per-warp histograms, bins 0..100
    __shared__ float hf[104];              // reduced histogram
    __shared__ float rocS[104];            // suffix sums S[j]
    __shared__ float redS[2 * NWARP];      // trapz block reduction

    const int tid = threadIdx.x;
    const int row = blockIdx.x;

    // Threshold table: replicate f32 jnp.linspace(0,1,100) exactly.
    if (tid < 101) {
        float tv = (float)tid * (1.0f / 99.0f);
        if (tid == 99)  tv = 1.0f;   // linspace endpoint (equals computed value anyway)
        if (tid == 100) tv = 2.0f;   // sentinel (never indexed, safety)
        tS[tid] = tv;
    }
    #pragma unroll
    for (int i = tid; i < NWARP * WSTRIDE; i += THREADS) wh[i] = 0.0f;
    __syncthreads();

    // Shared-space addresses, pre-biased by -1020 (idx4 >= 1020 always).
    const unsigned tb = (unsigned)__cvta_generic_to_shared(tS) - 1020u;
    const unsigned ab = (unsigned)__cvta_generic_to_shared(wh + (tid >> 5) * WSTRIDE) - 1020u;

    const float4* __restrict__ px = (const float4*)(x + (size_t)row * COLS);

    auto proc = [&](float v) {
        float w = __fmaf_rn(v, 0.38671875f, 2.9990234375f);   // 99/256, 3 - 2^-10
        unsigned idx4 = (__float_as_uint(w) >> 12) & 0xFFCu;  // 4*(k0+256)
        float thr;
        asm("ld.shared.f32 %0, [%1];" : "=f"(thr) : "r"(tb + idx4));
        unsigned a = ab + idx4 + ((v > thr) ? 4u : 0u);
        asm volatile("red.shared.add.f32 [%0], %1;" :: "r"(a), "f"(v));
    };

    // 16384 floats per row = 16 coalesced float4 iterations per thread.
    #pragma unroll 4
    for (int it = 0; it < COLS / (4 * THREADS); ++it) {
        float4 v4 = px[tid + (it << 8)];
        proc(v4.x); proc(v4.y); proc(v4.z); proc(v4.w);
    }
    __syncthreads();

    // Reduce per-warp histograms.
    if (tid < 101) {
        float s = 0.0f;
        #pragma unroll
        for (int w2 = 0; w2 < NWARP; ++w2) s += wh[w2 * WSTRIDE + tid];
        hf[tid] = s;
    }
    __syncthreads();

    // Suffix sums: full[j] = hf[j+1] (j<99), full[99] = hf[100];  rocS[j] = sum_{i>=j} full[i]
    if (tid == 0) {
        float run = hf[100];
        rocS[99] = run;
        #pragma unroll 1
        for (int j = 98; j >= 0; --j) { run += hf[j + 1]; rocS[j] = run; }
    }
    __syncthreads();

    const float invY = 1.0f / y[row];

    float c1 = 0.0f, c2 = 0.0f;
    if (tid < MCOL) {
        float r = rocS[tid] * invY;
        float d = ((tid < 99) ? hf[tid + 1] : (hf[98] + hf[99]) * 0.5f) * invY;
        out[(size_t)row * MCOL + tid]           = r;
        out[OUT_DER + (size_t)row * MCOL + tid] = d;
        // trapz = 0.5*f[0] + f[1..98] + 0.5*f[99]
        float wgt = (tid == 0 || tid == MCOL - 1) ? 0.5f : 1.0f;
        c1 = r * wgt;
        c2 = d * wgt;
    }
    // Block reduction of trapz contributions.
    #pragma unroll
    for (int o = 16; o > 0; o >>= 1) {
        c1 += __shfl_down_sync(0xFFFFFFFFu, c1, o);
        c2 += __shfl_down_sync(0xFFFFFFFFu, c2, o);
    }
    if ((tid & 31) == 0) {
        redS[tid >> 5]         = c1;
        redS[NWARP + (tid >> 5)] = c2;
    }
    __syncthreads();
    if (tid == 0) {
        float t1 = 0.0f, t2 = 0.0f;
        #pragma unroll
        for (int w2 = 0; w2 < NWARP; ++w2) { t1 += redS[w2]; t2 += redS[NWARP + w2]; }
        out[OUT_T1 + row] = t1;
        out[OUT_T2 + row] = t2;
    }
}

extern "C" void kernel_launch(void* const* d_in, const int* in_sizes, int n_in,
                              void* d_out, int out_size)
{
    const float* x = (const float*)d_in[0];
    const float* y = (const float*)d_in[1];
    roc_hist_kernel<<<ROWS, THREADS>>>(x, y, (float*)d_out);
}

// round 4
// speedup vs baseline: 1.1416x; 1.1416x over previous
#include <cuda_runtime.h>

// Problem constants (fixed shapes from reference)
#define ROWS    4096
#define COLS    16384
#define MCOL    100
#define THREADS 256
#define NWARP   (THREADS / 32)
#define WSTRIDE 104            // floats per per-warp histogram (bins 0..100, padded)

// Output layout: [roc (ROWS*100) | deriv (ROWS*100) | trapz_roc (ROWS) | trapz_deriv (ROWS)]
#define OUT_DER (ROWS * MCOL)
#define OUT_T1  (2 * ROWS * MCOL)
#define OUT_T2  (2 * ROWS * MCOL + ROWS)

// Binning (fully arithmetic, no shared-memory threshold table):
//   w  = fma(v, 99/256, 3 - 2^-10)  in [2.999, 3.386) c [2,4)   (single binade)
//   (bits(w) >> 14) & 0x3FF = 256 + k0,  k0 = floor(99v - 0.25)
//   wm = bits(w) & ~0x3FFF  ==  3 + k0 * 2^-8          (exact)
//   kf = fma(wm, 256, -768) ==  k0                      (exact)
//   thr= fma(kf, C, C)      ==  rn((k0+1)*C) == t[k0+1] (bit-identical to
//        f32 linspace entry: single rounding of the exact real (k0+1)*C)
//   bin = k0 + 1 + (v > thr)   -- exact searchsorted(t, v, 'left') semantics,
//        since the 0.25 shift guarantees true bin in {k0+1, k0+2}.
// idx4 = (wb>>12)&0xFFC = 4*(k0+256); histogram base pre-biased by -1020 so
// idx4 indexes hist[k0+1] directly.

__global__ void __launch_bounds__(THREADS, 1)
roc_hist_kernel(const float* __restrict__ x,
                const float* __restrict__ y,
                float* __restrict__ out)
{
    __shared__ float wh[NWARP * WSTRIDE];  // per-warp histograms, bins 0..100
    __shared__ float hf[104];              // reduced histogram
    __shared__ float rocS[104];            // suffix sums S[j]
    __shared__ float redS[2 * NWARP];      // trapz block reduction

    const int tid = threadIdx.x;
    const int row = blockIdx.x;

    #pragma unroll
    for (int i = tid; i < NWARP * WSTRIDE; i += THREADS) wh[i] = 0.0f;
    __syncthreads();

    // Per-warp histogram base, pre-biased by -1020 (idx4 >= 1020 always).
    const unsigned ab = (unsigned)__cvta_generic_to_shared(wh + (tid >> 5) * WSTRIDE) - 1020u;

    const float4* __restrict__ px = (const float4*)(x + (size_t)row * COLS);

    const float C = 1.0f / 99.0f;          // rn(1/99), matches linspace step

    auto proc = [&](float v) {
        float w = __fmaf_rn(v, 0.38671875f, 2.9990234375f);   // 99/256, 3 - 2^-10
        unsigned wb = __float_as_uint(w) & 0xFFFFC000u;
        float wm = __uint_as_float(wb);                        // 3 + k0/256 (exact)
        float kf = __fmaf_rn(wm, 256.0f, -768.0f);             // k0 (exact)
        float thr = __fmaf_rn(kf, C, C);                       // t[k0+1] (bit-exact)
        unsigned idx4 = (wb >> 12) & 0xFFCu;                   // 4*(k0+256)
        unsigned a = ab + idx4 + ((v > thr) ? 4u : 0u);
        asm volatile("red.shared.add.f32 [%0], %1;" :: "r"(a), "f"(v));
    };

    // 16384 floats per row = 16 coalesced float4 iterations per thread.
    #pragma unroll 4
    for (int it = 0; it < COLS / (4 * THREADS); ++it) {
        float4 v4 = px[tid + (it << 8)];
        proc(v4.x); proc(v4.y); proc(v4.z); proc(v4.w);
    }
    __syncthreads();

    // Reduce per-warp histograms.
    if (tid < 101) {
        float s = 0.0f;
        #pragma unroll
        for (int w2 = 0; w2 < NWARP; ++w2) s += wh[w2 * WSTRIDE + tid];
        hf[tid] = s;
    }
    __syncthreads();

    // Suffix sums: full[j] = hf[j+1] (j<99), full[99] = hf[100]; rocS[j] = sum_{i>=j} full[i]
    if (tid == 0) {
        float run = hf[100];
        rocS[99] = run;
        #pragma unroll 1
        for (int j = 98; j >= 0; --j) { run += hf[j + 1]; rocS[j] = run; }
    }
    __syncthreads();

    const float invY = 1.0f / y[row];

    float c1 = 0.0f, c2 = 0.0f;
    if (tid < MCOL) {
        float r = rocS[tid] * invY;
        float d = ((tid < 99) ? hf[tid + 1] : (hf[98] + hf[99]) * 0.5f) * invY;
        out[(size_t)row * MCOL + tid]           = r;
        out[OUT_DER + (size_t)row * MCOL + tid] = d;
        // trapz = 0.5*f[0] + f[1..98] + 0.5*f[99]
        float wgt = (tid == 0 || tid == MCOL - 1) ? 0.5f : 1.0f;
        c1 = r * wgt;
        c2 = d * wgt;
    }
    // Block reduction of trapz contributions.
    #pragma unroll
    for (int o = 16; o > 0; o >>= 1) {
        c1 += __shfl_down_sync(0xFFFFFFFFu, c1, o);
        c2 += __shfl_down_sync(0xFFFFFFFFu, c2, o);
    }
    if ((tid & 31) == 0) {
        redS[tid >> 5]           = c1;
        redS[NWARP + (tid >> 5)] = c2;
    }
    __syncthreads();
    if (tid == 0) {
        float t1 = 0.0f, t2 = 0.0f;
        #pragma unroll
        for (int w2 = 0; w2 < NWARP; ++w2) { t1 += redS[w2]; t2 += redS[NWARP + w2]; }
        out[OUT_T1 + row] = t1;
        out[OUT_T2 + row] = t2;
    }
}

extern "C" void kernel_launch(void* const* d_in, const int* in_sizes, int n_in,
                              void* d_out, int out_size)
{
    const float* x = (const float*)d_in[0];
    const float* y = (const float*)d_in[1];
    roc_hist_kernel<<<ROWS, THREADS>>>(x, y, (float*)d_out);
}

// round 5
// speedup vs baseline: 1.8481x; 1.6188x over previous
#include <cuda_runtime.h>

// Problem constants (fixed shapes from reference)
#define ROWS    4096
#define COLS    16384
#define MCOL    100
#define THREADS 256
#define NWARP   (THREADS / 32)
#define NCOPY   64             // histogram copies; c = tid & 63 -> bank = lane (conflict-free)

// Output layout: [roc (ROWS*100) | deriv (ROWS*100) | trapz_roc (ROWS) | trapz_deriv (ROWS)]
#define OUT_DER (ROWS * MCOL)
#define OUT_T1  (2 * ROWS * MCOL)
#define OUT_T2  (2 * ROWS * MCOL + ROWS)

// Binning (fully arithmetic, no shared threshold table) — see R2 proof:
//   w  = fma(v, 99/256, 3 - 2^-10) in [2.999, 3.386) c [2,4)
//   k0 = floor(99v - 0.25);  wm = bits(w) & ~0x3FFF == 3 + k0/256 (exact)
//   kf = fma(wm, 256, -768) == k0 (exact);  thr = fma(kf, C, C) == t[k0+1] bit-exact
//   bin = k0 + 1 + (v > thr)  -- exact searchsorted(t, v, 'left') semantics.
//
// Histogram layout: wh[k][c], c = tid & 63. Byte address = k*256 + 4c.
// Bank = (k*64 + c) mod 32 = c mod 32 = lane  => RED.shared has ZERO bank
// conflicts for any bin pattern (the R4 binder was ~3.3 replay wavefronts per
// warp-RED from random banks). 4 warps share each copy-set; RED keeps atomicity.
// idx256 = (bits(w)>>6) & 0x3FF00 = 256*(k0+256); base pre-biased by
// 4c + 256 - 65536 so idx256 indexes wh[k0+1][c] directly.

__global__ void __launch_bounds__(THREADS, 1)
roc_hist_kernel(const float* __restrict__ x,
                const float* __restrict__ y,
                float* __restrict__ out)
{
    __shared__ __align__(128) float wh[(MCOL + 1) * NCOPY];  // 101*64 = 25.9 KB
    __shared__ float hf[104];              // reduced histogram
    __shared__ float rocS[104];            // suffix sums S[j]
    __shared__ float redS[2 * NWARP];      // trapz block reduction

    const int tid  = threadIdx.x;
    const int lane = tid & 31;
    const int row  = blockIdx.x;

    #pragma unroll
    for (int i = tid; i < (MCOL + 1) * NCOPY; i += THREADS) wh[i] = 0.0f;
    __syncthreads();

    // Copy base, pre-biased: +4*(tid&63) selects this thread's copy column,
    // +256-65536 debiases idx256 (min 65280) and lands on bin k0+1.
    const unsigned cb = (unsigned)__cvta_generic_to_shared(wh)
                      + 4u * (unsigned)(tid & 63) + 256u - 65536u;

    const float4* __restrict__ px = (const float4*)(x + (size_t)row * COLS);

    const float C = 1.0f / 99.0f;          // rn(1/99), matches linspace step

    auto proc = [&](float v) {
        float w = __fmaf_rn(v, 0.38671875f, 2.9990234375f);    // 99/256, 3 - 2^-10
        unsigned wb = __float_as_uint(w);
        float wm = __uint_as_float(wb & 0xFFFFC000u);           // 3 + k0/256 (exact)
        float kf = __fmaf_rn(wm, 256.0f, -768.0f);              // k0 (exact)
        float thr = __fmaf_rn(kf, C, C);                        // t[k0+1] (bit-exact)
        unsigned idx256 = (wb >> 6) & 0x3FF00u;                 // 256*(k0+256)
        unsigned a = cb + idx256 + ((v > thr) ? 256u : 0u);
        asm volatile("red.shared.add.f32 [%0], %1;" :: "r"(a), "f"(v));
    };

    // 16384 floats per row = 16 coalesced float4 iterations per thread.
    #pragma unroll 4
    for (int it = 0; it < COLS / (4 * THREADS); ++it) {
        float4 v4 = px[tid + (it << 8)];
        proc(v4.x); proc(v4.y); proc(v4.z); proc(v4.w);
    }
    __syncthreads();

    // Reduce the 64 copies per bin. Lane-rotated order keeps LDS conflict-free:
    // address = k*64 + ((lane+j)&63)  ->  bank = (lane+j)&31, unique per lane.
    if (tid < MCOL + 1) {
        const float* hk = wh + tid * NCOPY;
        float s = 0.0f;
        int c = lane;
        #pragma unroll
        for (int j = 0; j < NCOPY; ++j) {
            s += hk[c];
            c = (c + 1) & (NCOPY - 1);
        }
        hf[tid] = s;
    }
    __syncthreads();

    // Suffix sums: full[j] = hf[j+1] (j<99), full[99] = hf[100]; rocS[j] = sum_{i>=j} full[i]
    if (tid == 0) {
        float run = hf[100];
        rocS[99] = run;
        #pragma unroll 1
        for (int j = 98; j >= 0; --j) { run += hf[j + 1]; rocS[j] = run; }
    }
    __syncthreads();

    const float invY = 1.0f / y[row];

    float c1 = 0.0f, c2 = 0.0f;
    if (tid < MCOL) {
        float r = rocS[tid] * invY;
        float d = ((tid < 99) ? hf[tid + 1] : (hf[98] + hf[99]) * 0.5f) * invY;
        out[(size_t)row * MCOL + tid]           = r;
        out[OUT_DER + (size_t)row * MCOL + tid] = d;
        // trapz = 0.5*f[0] + f[1..98] + 0.5*f[99]
        float wgt = (tid == 0 || tid == MCOL - 1) ? 0.5f : 1.0f;
        c1 = r * wgt;
        c2 = d * wgt;
    }
    // Block reduction of trapz contributions.
    #pragma unroll
    for (int o = 16; o > 0; o >>= 1) {
        c1 += __shfl_down_sync(0xFFFFFFFFu, c1, o);
        c2 += __shfl_down_sync(0xFFFFFFFFu, c2, o);
    }
    if (lane == 0) {
        redS[tid >> 5]           = c1;
        redS[NWARP + (tid >> 5)] = c2;
    }
    __syncthreads();
    if (tid == 0) {
        float t1 = 0.0f, t2 = 0.0f;
        #pragma unroll
        for (int w2 = 0; w2 < NWARP; ++w2) { t1 += redS[w2]; t2 += redS[NWARP + w2]; }
        out[OUT_T1 + row] = t1;
        out[OUT_T2 + row] = t2;
    }
}

extern "C" void kernel_launch(void* const* d_in, const int* in_sizes, int n_in,
                              void* d_out, int out_size)
{
    const float* x = (const float*)d_in[0];
    const float* y = (const float*)d_in[1];
    roc_hist_kernel<<<ROWS, THREADS>>>(x, y, (float*)d_out);
}

// round 7
// speedup vs baseline: 2.0367x; 1.1021x over previous
#include <cuda_runtime.h>

// Problem constants (fixed shapes from reference)
#define ROWS    4096
#define COLS    16384
#define MCOL    100
#define THREADS 256
#define NWARP   (THREADS / 32)
#define NCOPY   64             // histogram copies; c = tid & 63 -> bank = lane (conflict-free)

// Output layout: [roc (ROWS*100) | deriv (ROWS*100) | trapz_roc (ROWS) | trapz_deriv (ROWS)]
#define OUT_DER (ROWS * MCOL)
#define OUT_T1  (2 * ROWS * MCOL)
#define OUT_T2  (2 * ROWS * MCOL + ROWS)

// Binning (fully arithmetic, bit-exact searchsorted; proof in R2 header):
//   w  = fma(v, 99/256, 3 - 2^-10);  k0 = floor(99v - 0.25)
//   wm = bits(w) & ~0x3FFF == 3 + k0/256 (exact); kf = fma(wm,256,-768) == k0
//   thr = fma(kf, C, C) == rn((k0+1)C) == t[k0+1] bit-exact
//   bin = k0 + 1 + (v > thr)
// The three FFMAs run as packed fma.rn.f32x2 over element pairs (Blackwell).
//
// Histogram: wh[k][c], c = tid&63, addr = k*256 + 4c -> bank = lane for every
// lane => RED.shared structurally conflict-free (R5 win).

__global__ void __launch_bounds__(THREADS, 1)
roc_hist_kernel(const float* __restrict__ x,
                const float* __restrict__ y,
                float* __restrict__ out)
{
    __shared__ __align__(128) float wh[(MCOL + 1) * NCOPY];  // 101*64 = 25.9 KB
    __shared__ float hf[104];              // reduced histogram
    __shared__ float rocS[104];            // suffix sums S[j]
    __shared__ float redS[2 * NWARP];      // trapz block reduction

    const int tid  = threadIdx.x;
    const int lane = tid & 31;
    const int row  = blockIdx.x;

    #pragma unroll
    for (int i = tid; i < (MCOL + 1) * NCOPY; i += THREADS) wh[i] = 0.0f;
    __syncthreads();

    // Copy base, pre-biased: +4*(tid&63) selects the copy column,
    // +256-65536 debiases idx256 (min 65280) and lands on bin k0+1.
    const unsigned cb = (unsigned)__cvta_generic_to_shared(wh)
                      + 4u * (unsigned)(tid & 63) + 256u - 65536u;

    const float4* __restrict__ px = (const float4*)(x + (size_t)row * COLS);

    // Packed constants (lo == hi) for fma.rn.f32x2.
    unsigned long long KB, BB, K256, M768, CC2;
    asm("mov.b64 %0, {%1, %1};" : "=l"(KB)   : "f"(0.38671875f));     // 99/256
    asm("mov.b64 %0, {%1, %1};" : "=l"(BB)   : "f"(2.9990234375f));   // 3 - 2^-10
    asm("mov.b64 %0, {%1, %1};" : "=l"(K256) : "f"(256.0f));
    asm("mov.b64 %0, {%1, %1};" : "=l"(M768) : "f"(-768.0f));
    asm("mov.b64 %0, {%1, %1};" : "=l"(CC2)  : "f"(1.0f / 99.0f));    // rn(1/99)

    // Bin an element pair with packed math, then RED each into shared.
    auto proc2 = [&](float v0, float v1) {
        unsigned long long v01, w01, wm01, kf01, thr01;
        asm("mov.b64 %0, {%1, %2};" : "=l"(v01) : "f"(v0), "f"(v1));
        asm("fma.rn.f32x2 %0, %1, %2, %3;" : "=l"(w01)  : "l"(v01),  "l"(KB),   "l"(BB));
        unsigned wb0, wb1;
        asm("mov.b64 {%0, %1}, %2;" : "=r"(wb0), "=r"(wb1) : "l"(w01));
        unsigned wmb0 = wb0 & 0xFFFFC000u;
        unsigned wmb1 = wb1 & 0xFFFFC000u;
        asm("mov.b64 %0, {%1, %2};" : "=l"(wm01) : "r"(wmb0), "r"(wmb1));
        asm("fma.rn.f32x2 %0, %1, %2, %3;" : "=l"(kf01)  : "l"(wm01), "l"(K256), "l"(M768));
        asm("fma.rn.f32x2 %0, %1, %2, %3;" : "=l"(thr01) : "l"(kf01), "l"(CC2),  "l"(CC2));
        float thr0, thr1;
        asm("mov.b64 {%0, %1}, %2;" : "=f"(thr0), "=f"(thr1) : "l"(thr01));
        unsigned a0 = cb + ((wb0 >> 6) & 0x3FF00u) + ((v0 > thr0) ? 256u : 0u);
        unsigned a1 = cb + ((wb1 >> 6) & 0x3FF00u) + ((v1 > thr1) ? 256u : 0u);
        asm volatile("red.shared.add.f32 [%0], %1;" :: "r"(a0), "f"(v0));
        asm volatile("red.shared.add.f32 [%0], %1;" :: "r"(a1), "f"(v1));
    };

    // 16 float4 iterations per thread; prefetch next LDG.128 before processing
    // the current one so the load is always in flight (long-scoreboard cover).
    float4 cur = px[tid];
    #pragma unroll
    for (int it = 0; it < COLS / (4 * THREADS) - 1; ++it) {
        float4 nxt = px[tid + ((it + 1) << 8)];
        proc2(cur.x, cur.y);
        proc2(cur.z, cur.w);
        cur = nxt;
    }
    proc2(cur.x, cur.y);
    proc2(cur.z, cur.w);
    __syncthreads();

    // Reduce the 64 copies per bin. Lane-rotated order keeps LDS conflict-free.
    if (tid < MCOL + 1) {
        const float* hk = wh + tid * NCOPY;
        float s = 0.0f;
        int c = lane;
        #pragma unroll
        for (int j = 0; j < NCOPY; ++j) {
            s += hk[c];
            c = (c + 1) & (NCOPY - 1);
        }
        hf[tid] = s;
    }
    __syncthreads();

    // Suffix sums: full[j] = hf[j+1] (j<99), full[99] = hf[100]; rocS[j] = sum_{i>=j} full[i]
    if (tid == 0) {
        float run = hf[100];
        rocS[99] = run;
        #pragma unroll 1
        for (int j = 98; j >= 0; --j) { run += hf[j + 1]; rocS[j] = run; }
    }
    __syncthreads();

    const float invY = 1.0f / y[row];

    float c1 = 0.0f, c2 = 0.0f;
    if (tid < MCOL) {
        float r = rocS[tid] * invY;
        float d = ((tid < 99) ? hf[tid + 1] : (hf[98] + hf[99]) * 0.5f) * invY;
        out[(size_t)row * MCOL + tid]           = r;
        out[OUT_DER + (size_t)row * MCOL + tid] = d;
        // trapz = 0.5*f[0] + f[1..98] + 0.5*f[99]
        float wgt = (tid == 0 || tid == MCOL - 1) ? 0.5f : 1.0f;
        c1 = r * wgt;
        c2 = d * wgt;
    }
    // Block reduction of trapz contributions.
    #pragma unroll
    for (int o = 16; o > 0; o >>= 1) {
        c1 += __shfl_down_sync(0xFFFFFFFFu, c1, o);
        c2 += __shfl_down_sync(0xFFFFFFFFu, c2, o);
    }
    if (lane == 0) {
        redS[tid >> 5]           = c1;
        redS[NWARP + (tid >> 5)] = c2;
    }
    __syncthreads();
    if (tid == 0) {
        float t1 = 0.0f, t2 = 0.0f;
        #pragma unroll
        for (int w2 = 0; w2 < NWARP; ++w2) { t1 += redS[w2]; t2 += redS[NWARP + w2]; }
        out[OUT_T1 + row] = t1;
        out[OUT_T2 + row] = t2;
    }
}

extern "C" void kernel_launch(void* const* d_in, const int* in_sizes, int n_in,
                              void* d_out, int out_size)
{
    const float* x = (const float*)d_in[0];
    const float* y = (const float*)d_in[1];
    roc_hist_kernel<<<ROWS, THREADS>>>(x, y, (float*)d_out);
}

// round 8
// speedup vs baseline: 2.2264x; 1.0931x over previous
#include <cuda_runtime.h>

// Problem constants (fixed shapes from reference)
#define ROWS    4096
#define COLS    16384
#define MCOL    100
#define THREADS 256
#define NWARP   (THREADS / 32)
#define NCOPY   32             // histogram copies; c = lane -> bank = lane (conflict-free)

// Output layout: [roc (ROWS*100) | deriv (ROWS*100) | trapz_roc (ROWS) | trapz_deriv (ROWS)]
#define OUT_DER (ROWS * MCOL)
#define OUT_T1  (2 * ROWS * MCOL)
#define OUT_T2  (2 * ROWS * MCOL + ROWS)

// Binning (fully arithmetic, bit-exact searchsorted; proof in R2 header):
//   w  = fma(v, 99/256, 3 - 2^-10);  k0 = floor(99v - 0.25)
//   wm = bits(w) & ~0x3FFF == 3 + k0/256 (exact); kf = fma(wm,256,-768) == k0
//   thr = fma(kf, C, C) == rn((k0+1)C) == t[k0+1] bit-exact
//   bin = k0 + 1 + (v > thr)
// Three FFMAs run as packed fma.rn.f32x2 over element pairs.
//
// Histogram: wh[k][c], c = lane, byte addr = k*128 + 4c -> bank = lane for
// every lane => RED.shared structurally conflict-free (R5 win). 8 warps share
// the 32 copies; cross-warp same-address collisions ~1% (harmless).
// idx128 = (bits(w)>>7) & 0x1FF80 = 128*(k0+256); base pre-biased by
// 4*lane + 128 - 32768 so idx128 indexes wh[k0+1][lane] directly.

__global__ void __launch_bounds__(THREADS, 1)
roc_hist_kernel(const float* __restrict__ x,
                const float* __restrict__ y,
                float* __restrict__ out)
{
    __shared__ __align__(128) float wh[(MCOL + 1) * NCOPY];  // 101*32 = 12.9 KB
    __shared__ float hf[104];              // reduced histogram
    __shared__ float warpT[4];             // suffix-scan warp totals
    __shared__ float redS[2 * NWARP];      // trapz block reduction

    const int tid  = threadIdx.x;
    const int lane = tid & 31;
    const int wid  = tid >> 5;
    const int row  = blockIdx.x;

    #pragma unroll
    for (int i = tid; i < (MCOL + 1) * NCOPY; i += THREADS) wh[i] = 0.0f;
    __syncthreads();

    // Copy base, pre-biased: +4*lane selects the copy column,
    // +128-32768 debiases idx128 (min 32640) and lands on bin k0+1.
    const unsigned cb = (unsigned)__cvta_generic_to_shared(wh)
                      + 4u * (unsigned)lane + 128u - 32768u;

    const float4* __restrict__ px = (const float4*)(x + (size_t)row * COLS);

    // Packed constants (lo == hi) for fma.rn.f32x2.
    unsigned long long KB, BB, K256, M768, CC2;
    asm("mov.b64 %0, {%1, %1};" : "=l"(KB)   : "f"(0.38671875f));     // 99/256
    asm("mov.b64 %0, {%1, %1};" : "=l"(BB)   : "f"(2.9990234375f));   // 3 - 2^-10
    asm("mov.b64 %0, {%1, %1};" : "=l"(K256) : "f"(256.0f));
    asm("mov.b64 %0, {%1, %1};" : "=l"(M768) : "f"(-768.0f));
    asm("mov.b64 %0, {%1, %1};" : "=l"(CC2)  : "f"(1.0f / 99.0f));    // rn(1/99)

    // Bin an element pair with packed math, then RED each into shared.
    auto proc2 = [&](float v0, float v1) {
        unsigned long long v01, w01, wm01, kf01, thr01;
        asm("mov.b64 %0, {%1, %2};" : "=l"(v01) : "f"(v0), "f"(v1));
        asm("fma.rn.f32x2 %0, %1, %2, %3;" : "=l"(w01)  : "l"(v01),  "l"(KB),   "l"(BB));
        unsigned wb0, wb1;
        asm("mov.b64 {%0, %1}, %2;" : "=r"(wb0), "=r"(wb1) : "l"(w01));
        unsigned wmb0 = wb0 & 0xFFFFC000u;
        unsigned wmb1 = wb1 & 0xFFFFC000u;
        asm("mov.b64 %0, {%1, %2};" : "=l"(wm01) : "r"(wmb0), "r"(wmb1));
        asm("fma.rn.f32x2 %0, %1, %2, %3;" : "=l"(kf01)  : "l"(wm01), "l"(K256), "l"(M768));
        asm("fma.rn.f32x2 %0, %1, %2, %3;" : "=l"(thr01) : "l"(kf01), "l"(CC2),  "l"(CC2));
        float thr0, thr1;
        asm("mov.b64 {%0, %1}, %2;" : "=f"(thr0), "=f"(thr1) : "l"(thr01));
        unsigned a0 = cb + ((wb0 >> 7) & 0x1FF80u) + ((v0 > thr0) ? 128u : 0u);
        unsigned a1 = cb + ((wb1 >> 7) & 0x1FF80u) + ((v1 > thr1) ? 128u : 0u);
        asm volatile("red.shared.add.f32 [%0], %1;" :: "r"(a0), "f"(v0));
        asm volatile("red.shared.add.f32 [%0], %1;" :: "r"(a1), "f"(v1));
    };

    // 16 float4 iterations per thread; keep TWO LDG.128 in flight.
    float4 c0 = px[tid];
    float4 c1 = px[tid + 256];
    #pragma unroll
    for (int it = 0; it < COLS / (4 * THREADS) - 2; ++it) {
        float4 nx = px[tid + ((it + 2) << 8)];
        proc2(c0.x, c0.y);
        proc2(c0.z, c0.w);
        c0 = c1; c1 = nx;
    }
    proc2(c0.x, c0.y); proc2(c0.z, c0.w);
    proc2(c1.x, c1.y); proc2(c1.z, c1.w);
    __syncthreads();

    // Reduce 32 copies per bin with rotated LDS.128 (conflict-free: within an
    // 8-lane phase, e=(tid+j)&7 is distinct -> banks 4e..4e+3 cover all 32).
    if (tid < MCOL + 1) {
        const float4* hk4 = (const float4*)(wh + tid * NCOPY);
        float s = 0.0f;
        #pragma unroll
        for (int j = 0; j < 8; ++j) {
            float4 t = hk4[(tid + j) & 7];
            s += (t.x + t.y) + (t.z + t.w);
        }
        hf[tid] = s;
    }
    __syncthreads();

    // Parallel suffix sum over full[j] (j=0..99), full[j]=hf[j+1] (j<99),
    // full[99]=hf[100]. Warps 0..3 cover positions 0..127 (>=100 hold 0).
    float f = 0.0f;
    if (tid < 99)       f = hf[tid + 1];
    else if (tid == 99) f = hf[100];
    #pragma unroll
    for (int off = 1; off < 32; off <<= 1) {
        float g = __shfl_down_sync(0xFFFFFFFFu, f, off);
        if (lane < 32 - off) f += g;
    }
    if (wid < 4 && lane == 0) warpT[wid] = f;   // warp suffix total (pos 32w..)
    // re-broadcast intra-warp suffix to all lanes is already in f
    __syncthreads();
    #pragma unroll
    for (int w2 = 0; w2 < 4; ++w2)
        if (w2 > wid) f += warpT[w2];
    // f == rocS[tid] for tid < 100

    const float invY = 1.0f / y[row];

    float c1s = 0.0f, c2s = 0.0f;
    if (tid < MCOL) {
        float r = f * invY;
        float d = ((tid < 99) ? hf[tid + 1] : (hf[98] + hf[99]) * 0.5f) * invY;
        out[(size_t)row * MCOL + tid]           = r;
        out[OUT_DER + (size_t)row * MCOL + tid] = d;
        // trapz = 0.5*f[0] + f[1..98] + 0.5*f[99]
        float wgt = (tid == 0 || tid == MCOL - 1) ? 0.5f : 1.0f;
        c1s = r * wgt;
        c2s = d * wgt;
    }
    // Block reduction of trapz contributions (warps 4..7 contribute zeros).
    #pragma unroll
    for (int o = 16; o > 0; o >>= 1) {
        c1s += __shfl_down_sync(0xFFFFFFFFu, c1s, o);
        c2s += __shfl_down_sync(0xFFFFFFFFu, c2s, o);
    }
    if (lane == 0) {
        redS[wid]         = c1s;
        redS[NWARP + wid] = c2s;
    }
    __syncthreads();
    if (tid == 0) {
        float t1 = 0.0f, t2 = 0.0f;
        #pragma unroll
        for (int w2 = 0; w2 < NWARP; ++w2) { t1 += redS[w2]; t2 += redS[NWARP + w2]; }
        out[OUT_T1 + row] = t1;
        out[OUT_T2 + row] = t2;
    }
}

extern "C" void kernel_launch(void* const* d_in, const int* in_sizes, int n_in,
                              void* d_out, int out_size)
{
    const float* x = (const float*)d_in[0];
    const float* y = (const float*)d_in[1];
    roc_hist_kernel<<<ROWS, THREADS>>>(x, y, (float*)d_out);
}